// round 2
// baseline (speedup 1.0000x reference)
#include <cuda_runtime.h>
#include <cstdint>

// Problem constants (fixed shape (8,2048,2048) fp32, ratio 0.1)
#define N_ELEMS   33554432
#define N_VEC4    (N_ELEMS / 4)
#define K_TOP     3355443           // int(0.1 * N)
#define SBINS     8192              // sample histogram bins (13 bits of 31-bit key)
#define SSHIFT    18                // 31-bit key >> 18 -> 13-bit bin
#define WIN_BINS  (1 << 20)         // exact window histogram: 4 coarse bins * 2^18
#define WCHUNK    1024              // window scan chunk size
#define NCHUNKS   (WIN_BINS / WCHUNK)
#define EQ_CAP    65536
#define SAMPLE_V4 262144            // 1/32 of float4s sampled
#define STARGET   (K_TOP / 32)      // sample-space rank target

__device__ unsigned int g_shist[SBINS];
__device__ unsigned int g_winHist[WIN_BINS];
__device__ unsigned int g_chunkSum[NCHUNKS];
__device__ unsigned int g_above;
__device__ unsigned int g_lo;
__device__ unsigned int g_T;
__device__ unsigned int g_need;
__device__ unsigned int g_eqCount;
__device__ unsigned int g_eqIdx[EQ_CAP];

// ---------------------------------------------------------------------------
// Zero the scratch state that must be reset every replay.
__global__ void k_zero() {
    int tid = blockIdx.x * blockDim.x + threadIdx.x;
    int stride = gridDim.x * blockDim.x;
    for (int i = tid; i < WIN_BINS; i += stride) g_winHist[i] = 0;
    for (int i = tid; i < SBINS; i += stride) g_shist[i] = 0;
    if (tid == 0) { g_above = 0; g_eqCount = 0; }
}

// ---------------------------------------------------------------------------
// Sample 1/32 of the data (64 consecutive float4 out of every 2048) into a
// 13-bit shared-memory histogram, flush to global.
__global__ void k_sample(const float4* __restrict__ x) {
    __shared__ unsigned int sh[SBINS];
    for (int i = threadIdx.x; i < SBINS; i += blockDim.x) sh[i] = 0;
    __syncthreads();

    int tid = blockIdx.x * blockDim.x + threadIdx.x;
    int stride = gridDim.x * blockDim.x;
    for (int i = tid; i < SAMPLE_V4; i += stride) {
        int p = ((i >> 6) << 11) + (i & 63);   // 64 f4 per 2048-f4 group
        float4 v = x[p];
        atomicAdd(&sh[(__float_as_uint(v.x) & 0x7FFFFFFFu) >> SSHIFT], 1u);
        atomicAdd(&sh[(__float_as_uint(v.y) & 0x7FFFFFFFu) >> SSHIFT], 1u);
        atomicAdd(&sh[(__float_as_uint(v.z) & 0x7FFFFFFFu) >> SSHIFT], 1u);
        atomicAdd(&sh[(__float_as_uint(v.w) & 0x7FFFFFFFu) >> SSHIFT], 1u);
    }
    __syncthreads();
    for (int i = threadIdx.x; i < SBINS; i += blockDim.x) {
        unsigned int c = sh[i];
        if (c) atomicAdd(&g_shist[i], c);
    }
}

// ---------------------------------------------------------------------------
// Scan the sample histogram from the top, find the coarse bin containing the
// estimated k-th value, and open a 4-coarse-bin (2^20 bit-values) window
// centered on it (±2 bins ≈ 39σ of sampling noise).
__global__ void k_sscan() {
    __shared__ unsigned int suf[1024];
    int t = threadIdx.x;
    unsigned int s = 0;
#pragma unroll
    for (int j = 0; j < 8; j++) s += g_shist[t * 8 + j];
    suf[t] = s;
    __syncthreads();
    // Hillis-Steele suffix scan: suf[t] = sum of partials t..1023
    for (int d = 1; d < 1024; d <<= 1) {
        unsigned int v = (t + d < 1024) ? suf[t + d] : 0;
        __syncthreads();
        suf[t] += v;
        __syncthreads();
    }
    // Find segment containing the crossing of STARGET (suffix counts from top)
    unsigned int segAbove = (t < 1023) ? suf[t + 1] : 0;
    if (suf[t] >= (unsigned)STARGET && segAbove < (unsigned)STARGET) {
        // walk this thread's 8 bins from the top
        unsigned int acc = segAbove;
        int bin = t * 8;
        for (int j = 7; j >= 0; j--) {
            acc += g_shist[t * 8 + j];
            if (acc >= (unsigned)STARGET) { bin = t * 8 + j; break; }
        }
        int lo_bin = bin >= 2 ? bin - 2 : 0;
        if (lo_bin > SBINS - 4) lo_bin = SBINS - 4;
        g_lo = (unsigned)lo_bin << SSHIFT;
    }
}

// ---------------------------------------------------------------------------
// One full pass: exact count of elements strictly above the window, plus an
// exact bit-level histogram of elements inside the window.
__global__ void k_count(const float4* __restrict__ x) {
    __shared__ unsigned int s_above;
    if (threadIdx.x == 0) s_above = 0;
    __syncthreads();

    unsigned int lo = g_lo;
    unsigned int hi = lo + WIN_BINS;
    unsigned int local = 0;

    int tid = blockIdx.x * blockDim.x + threadIdx.x;
    int stride = gridDim.x * blockDim.x;
    for (int i = tid; i < N_VEC4; i += stride) {
        float4 v = x[i];
        unsigned int b;
        b = __float_as_uint(v.x) & 0x7FFFFFFFu;
        if (b >= hi) local++; else if (b >= lo) atomicAdd(&g_winHist[b - lo], 1u);
        b = __float_as_uint(v.y) & 0x7FFFFFFFu;
        if (b >= hi) local++; else if (b >= lo) atomicAdd(&g_winHist[b - lo], 1u);
        b = __float_as_uint(v.z) & 0x7FFFFFFFu;
        if (b >= hi) local++; else if (b >= lo) atomicAdd(&g_winHist[b - lo], 1u);
        b = __float_as_uint(v.w) & 0x7FFFFFFFu;
        if (b >= hi) local++; else if (b >= lo) atomicAdd(&g_winHist[b - lo], 1u);
    }
#pragma unroll
    for (int off = 16; off; off >>= 1) local += __shfl_down_sync(0xFFFFFFFFu, local, off);
    if ((threadIdx.x & 31) == 0 && local) atomicAdd(&s_above, local);
    __syncthreads();
    if (threadIdx.x == 0 && s_above) atomicAdd(&g_above, s_above);
}

// ---------------------------------------------------------------------------
// Reduce the window histogram into 1024 chunk sums (one block per chunk).
__global__ void k_wreduce() {
    __shared__ unsigned int sm[256];
    unsigned int s = 0;
    int base = blockIdx.x * WCHUNK;
    for (int j = threadIdx.x; j < WCHUNK; j += 256) s += g_winHist[base + j];
    sm[threadIdx.x] = s;
    __syncthreads();
    for (int off = 128; off; off >>= 1) {
        if (threadIdx.x < off) sm[threadIdx.x] += sm[threadIdx.x + off];
        __syncthreads();
    }
    if (threadIdx.x == 0) g_chunkSum[blockIdx.x] = sm[0];
}

// ---------------------------------------------------------------------------
// Two-stage scan over the window histogram from the top: exact threshold T
// (31-bit key of the k-th largest), and tie budget `need` (= K - count(>T)).
__global__ void k_wscan() {
    __shared__ unsigned int suf[1024];
    __shared__ int s_c;
    int t = threadIdx.x;

    suf[t] = g_chunkSum[t];
    __syncthreads();
    for (int d = 1; d < 1024; d <<= 1) {
        unsigned int v = (t + d < 1024) ? suf[t + d] : 0;
        __syncthreads();
        suf[t] += v;
        __syncthreads();
    }
    unsigned int above = g_above;
    long long kRem = (long long)K_TOP - (long long)above;
    unsigned int winTotal = suf[0];

    if (kRem < 1) {                  // degenerate (window missed low) — approx
        if (t == 0) { g_T = g_lo + WIN_BINS - 1; g_need = 0; }
        return;
    }
    if (kRem > (long long)winTotal) { // degenerate (window missed high) — approx
        if (t == 0) { g_T = g_lo > 0 ? g_lo - 1 : 0; g_need = 0; }
        return;
    }
    // locate chunk containing the crossing
    unsigned int segAbove = (t < 1023) ? suf[t + 1] : 0;
    if ((long long)suf[t] >= kRem && (long long)segAbove < kRem) s_c = t;
    __syncthreads();
    int c = s_c;
    unsigned int baseAbove = (c < 1023) ? suf[c + 1] : 0;
    __syncthreads();

    // scan the 1024 bins of the winning chunk
    suf[t] = g_winHist[c * WCHUNK + t];
    __syncthreads();
    for (int d = 1; d < 1024; d <<= 1) {
        unsigned int v = (t + d < 1024) ? suf[t + d] : 0;
        __syncthreads();
        suf[t] += v;
        __syncthreads();
    }
    unsigned int binAbove = baseAbove + ((t < 1023) ? suf[t + 1] : 0);
    if ((long long)(baseAbove + suf[t]) >= kRem && (long long)binAbove < kRem) {
        unsigned int bin = (unsigned)c * WCHUNK + (unsigned)t;
        g_T = g_lo + bin;
        g_need = (unsigned)(kRem - (long long)binAbove);
    }
}

// ---------------------------------------------------------------------------
// Final pass: write output = x where bits > T else 0; record exact-tie indices.
__global__ void k_final(const float4* __restrict__ x, float4* __restrict__ out) {
    unsigned int T = g_T;
    int tid = blockIdx.x * blockDim.x + threadIdx.x;
    int stride = gridDim.x * blockDim.x;
    for (int i = tid; i < N_VEC4; i += stride) {
        float4 v = x[i];
        float4 o;
        unsigned int b;
        b = __float_as_uint(v.x) & 0x7FFFFFFFu;
        o.x = (b > T) ? v.x : 0.0f;
        if (b == T) { unsigned p = atomicAdd(&g_eqCount, 1u); if (p < EQ_CAP) g_eqIdx[p] = (unsigned)i * 4u + 0u; }
        b = __float_as_uint(v.y) & 0x7FFFFFFFu;
        o.y = (b > T) ? v.y : 0.0f;
        if (b == T) { unsigned p = atomicAdd(&g_eqCount, 1u); if (p < EQ_CAP) g_eqIdx[p] = (unsigned)i * 4u + 1u; }
        b = __float_as_uint(v.z) & 0x7FFFFFFFu;
        o.z = (b > T) ? v.z : 0.0f;
        if (b == T) { unsigned p = atomicAdd(&g_eqCount, 1u); if (p < EQ_CAP) g_eqIdx[p] = (unsigned)i * 4u + 2u; }
        b = __float_as_uint(v.w) & 0x7FFFFFFFu;
        o.w = (b > T) ? v.w : 0.0f;
        if (b == T) { unsigned p = atomicAdd(&g_eqCount, 1u); if (p < EQ_CAP) g_eqIdx[p] = (unsigned)i * 4u + 3u; }
        out[i] = o;
    }
}

// ---------------------------------------------------------------------------
// Resolve ties at the exact threshold value: keep the `need` smallest flat
// indices (matches lax.top_k stable tie-breaking). E is expected to be 1-2.
__global__ void k_tie(const float* __restrict__ x, float* __restrict__ out) {
    unsigned int cnt = g_eqCount;
    if (cnt > EQ_CAP) cnt = EQ_CAP;
    unsigned int need = g_need;
    if (need == 0 || cnt == 0) return;
    if (need >= cnt) {
        for (unsigned i = threadIdx.x; i < cnt; i += blockDim.x) {
            unsigned idx = g_eqIdx[i];
            out[idx] = x[idx];
        }
        return;
    }
    for (unsigned i = threadIdx.x; i < cnt; i += blockDim.x) {
        unsigned idx = g_eqIdx[i];
        unsigned r = 0;
        for (unsigned j = 0; j < cnt; j++) r += (g_eqIdx[j] < idx) ? 1u : 0u;
        if (r < need) out[idx] = x[idx];
    }
}

// ---------------------------------------------------------------------------
extern "C" void kernel_launch(void* const* d_in, const int* in_sizes, int n_in,
                              void* d_out, int out_size) {
    const float* x = (const float*)d_in[0];
    float* out = (float*)d_out;

    k_zero<<<256, 256>>>();
    k_sample<<<128, 256>>>((const float4*)x);
    k_sscan<<<1, 1024>>>();
    k_count<<<1184, 256>>>((const float4*)x);
    k_wreduce<<<NCHUNKS, 256>>>();
    k_wscan<<<1, 1024>>>();
    k_final<<<1184, 256>>>((const float4*)x, (float4*)out);
    k_tie<<<1, 256>>>(x, out);
}